// round 13
// baseline (speedup 1.0000x reference)
#include <cuda_runtime.h>

#define NN 65536
#define CC 64
#define KNN 16
#define EE (NN*KNN)
#define C8 8
#define PSTR 8192

// ---------------- scratch (device globals; no allocation allowed) ----------------
__device__ float g_y[NN*CC];      // x @ W_in^T (pre-BN)
__device__ float g_asrc[NN*CC];   // h @ src_w^T + src_b
__device__ float g_adst[NN*CC];   // h @ dst_w^T + dst_b
__device__ float g_hW[NN*CC];     // h @ lin_w^T + lin_b
__device__ float g_out[NN*CC];    // aggregated messages (pre-BN2)
__device__ float g_y3[NN*CC];     // h2 @ W_out^T (pre-BN3)
__device__ float g_a2pre[EE*C8];  // attn inner activations (pre-BN attn2)
__device__ float4 g_t4[EE];       // pre-BN pos-MLP output per edge
__device__ float g_part[128*PSTR];// transposed block partials: [stat][block]
__device__ float g_WT5[5*4096];   // pre-transposed weights: WT[k][j] per matrix

__device__ float g_bn1_s[CC], g_bn1_t[CC];
__device__ float g_pos_s[4],  g_pos_t[4];
__device__ float g_ab1_s[CC], g_ab1_t[CC];
__device__ float g_ab2_s[C8], g_ab2_t[C8];
__device__ float g_bn2_s[CC], g_bn2_t[CC];
__device__ float g_bn3_s[CC], g_bn3_t[CC];

// ---------------- weight pre-transpose: WT[k][j] = W[j][k], 5 matrices -----------
__global__ __launch_bounds__(256) void k_tw(
    const float* __restrict__ W0, const float* __restrict__ W1,
    const float* __restrict__ W2, const float* __restrict__ W3,
    const float* __restrict__ W4, float* __restrict__ out)
{
    const float* W = (blockIdx.x==0)?W0:(blockIdx.x==1)?W1:(blockIdx.x==2)?W2:(blockIdx.x==3)?W3:W4;
    float* o = out + blockIdx.x*4096;
    __shared__ float s[64*65];
    int tid = threadIdx.x;
    #pragma unroll
    for (int it = 0; it < 4; it++) {
        int f = it*1024 + tid*4;
        int j = f >> 6, k = f & 63;
        float4 v = *(const float4*)&W[j*64 + k];
        s[j*65+k]=v.x; s[j*65+k+1]=v.y; s[j*65+k+2]=v.z; s[j*65+k+3]=v.w;
    }
    __syncthreads();
    #pragma unroll
    for (int it = 0; it < 4; it++) {
        int f = it*1024 + tid*4;
        int k = f >> 6, j = f & 63;
        float4 v = make_float4(s[(j+0)*65+k], s[(j+1)*65+k], s[(j+2)*65+k], s[(j+3)*65+k]);
        *(float4*)&o[k*64 + j] = v;
    }
}

// swizzled X-tile store offset: element (c, r) lives at float index
//   (c)*64 + 4*((r/4 + c/4) & 15) + (r&3)
// store conflicts 2-way (was 8-way); float4 reads aligned & broadcast.

// ---------------- fused front: blocks 0..1023 GEMM1 (+bn1 partials),
//                  blocks 1024..2047 pos-MLP edge pass (+pos partials) ------------
__global__ __launch_bounds__(256) void k_front(
    const float* __restrict__ X, const float* __restrict__ WT,
    float* __restrict__ Y, float* __restrict__ part,
    const int* __restrict__ src, const float* __restrict__ pos,
    const float* __restrict__ pw1, const float* __restrict__ pb1)
{
    __shared__ float sXT[4096];
    __shared__ float sW[4096];
    __shared__ float sRed[16*128];
    const int tid = threadIdx.x;

    if (blockIdx.x < 1024) {
        const int row0 = blockIdx.x * 64;
        #pragma unroll
        for (int it = 0; it < 4; it++) {
            int flat = it*1024 + tid*4;
            int r = flat >> 6, c = flat & 63;
            float4 v = *(const float4*)&X[(row0 + r)*64 + c];
            int off = 4*(((r>>2) + (c>>2)) & 15) + (r & 3);
            sXT[(c+0)*64 + off] = v.x;
            sXT[(c+1)*64 + off] = v.y;
            sXT[(c+2)*64 + off] = v.z;
            sXT[(c+3)*64 + off] = v.w;
        }
        #pragma unroll
        for (int it = 0; it < 4; it++) {
            int flat = it*1024 + tid*4;
            *(float4*)&sW[flat] = *(const float4*)&WT[flat];
        }
        __syncthreads();

        const int tr = tid >> 4, tc = tid & 15;
        const int r0 = tr * 4, c0 = tc * 4;
        float acc[4][4];
        #pragma unroll
        for (int i = 0; i < 4; i++)
            #pragma unroll
            for (int j = 0; j < 4; j++) acc[i][j] = 0.f;

        #pragma unroll 8
        for (int k = 0; k < 64; k++) {
            float4 xv = *(const float4*)&sXT[k*64 + 4*((tr + (k>>2)) & 15)];
            float4 wv = *(const float4*)&sW[k*64 + c0];
            float xa[4] = {xv.x, xv.y, xv.z, xv.w};
            float wa[4] = {wv.x, wv.y, wv.z, wv.w};
            #pragma unroll
            for (int i = 0; i < 4; i++)
                #pragma unroll
                for (int j = 0; j < 4; j++) acc[i][j] = fmaf(xa[i], wa[j], acc[i][j]);
        }
        float cs[4] = {0,0,0,0}, cq[4] = {0,0,0,0};
        #pragma unroll
        for (int i = 0; i < 4; i++) {
            float4 v4 = make_float4(acc[i][0], acc[i][1], acc[i][2], acc[i][3]);
            *(float4*)&Y[(row0 + r0 + i)*64 + c0] = v4;
            #pragma unroll
            for (int j = 0; j < 4; j++) { cs[j] += acc[i][j]; cq[j] += acc[i][j]*acc[i][j]; }
        }
        #pragma unroll
        for (int j = 0; j < 4; j++) {
            sRed[tr*128 + c0 + j]      = cs[j];
            sRed[tr*128 + 64 + c0 + j] = cq[j];
        }
        __syncthreads();
        if (tid < 128) {
            float p = 0.f;
            #pragma unroll 4
            for (int r = 0; r < 16; r++) p += sRed[r*128 + tid];
            part[tid*PSTR + blockIdx.x] = p;
        }
    } else {
        const int bid = blockIdx.x - 1024;
        float w0=pw1[0],w1=pw1[1],w2=pw1[2],w3=pw1[3],w4=pw1[4],w5=pw1[5],w6=pw1[6],w7=pw1[7],w8=pw1[8];
        float b0=pb1[0],b1=pb1[1],b2=pb1[2];
        float s0=0,s1=0,s2=0,q0=0,q1=0,q2=0;
        int stride = 1024 * 256;
        for (int e = bid*256 + tid; e < EE; e += stride) {
            int sp = src[e]*3, np = (e >> 4)*3;
            float rx = pos[sp]-pos[np], ry = pos[sp+1]-pos[np+1], rz = pos[sp+2]-pos[np+2];
            float t0 = fmaf(w0,rx,fmaf(w1,ry,fmaf(w2,rz,b0)));
            float t1 = fmaf(w3,rx,fmaf(w4,ry,fmaf(w5,rz,b1)));
            float t2 = fmaf(w6,rx,fmaf(w7,ry,fmaf(w8,rz,b2)));
            g_t4[e] = make_float4(t0, t1, t2, 0.f);
            s0+=t0; s1+=t1; s2+=t2; q0+=t0*t0; q1+=t1*t1; q2+=t2*t2;
        }
        #pragma unroll
        for (int off=16; off>0; off>>=1) {
            s0+=__shfl_xor_sync(0xffffffffu,s0,off); s1+=__shfl_xor_sync(0xffffffffu,s1,off);
            s2+=__shfl_xor_sync(0xffffffffu,s2,off); q0+=__shfl_xor_sync(0xffffffffu,q0,off);
            q1+=__shfl_xor_sync(0xffffffffu,q1,off); q2+=__shfl_xor_sync(0xffffffffu,q2,off);
        }
        int wp = tid>>5;
        if ((tid&31)==0){ sRed[wp*8+0]=s0; sRed[wp*8+1]=s1; sRed[wp*8+2]=s2;
                          sRed[wp*8+4]=q0; sRed[wp*8+5]=q1; sRed[wp*8+6]=q2; }
        __syncthreads();
        if (tid < 128) {
            float p = 0.f;
            if (tid < 3)                    { for (int w=0;w<8;w++) p += sRed[w*8+tid]; }
            else if (tid >= 64 && tid < 67) { for (int w=0;w<8;w++) p += sRed[w*8+4+(tid-64)]; }
            g_part[tid*PSTR + 1024 + bid] = p;
        }
    }
}

// ---------------- fused triple GEMM: Y_m = relu(bn(X)) @ W_m^T + b_m -------------
__global__ __launch_bounds__(256) void k_gemm3(
    const float* __restrict__ X,
    const float* __restrict__ WT0, const float* __restrict__ WT1, const float* __restrict__ WT2,
    const float* __restrict__ b0, const float* __restrict__ b1, const float* __restrict__ b2,
    const float* __restrict__ ts, const float* __restrict__ tt,
    float* __restrict__ Y0, float* __restrict__ Y1, float* __restrict__ Y2)
{
    __shared__ float sXT[4096];
    __shared__ float sW[4096];
    const int tid = threadIdx.x;
    const int row0 = blockIdx.x * 64;

    #pragma unroll
    for (int it = 0; it < 4; it++) {
        int flat = it*1024 + tid*4;
        int r = flat >> 6, c = flat & 63;
        float4 v = *(const float4*)&X[(row0 + r)*64 + c];
        v.x = fmaxf(fmaf(v.x, ts[c],   tt[c]),   0.f);
        v.y = fmaxf(fmaf(v.y, ts[c+1], tt[c+1]), 0.f);
        v.z = fmaxf(fmaf(v.z, ts[c+2], tt[c+2]), 0.f);
        v.w = fmaxf(fmaf(v.w, ts[c+3], tt[c+3]), 0.f);
        int off = 4*(((r>>2) + (c>>2)) & 15) + (r & 3);
        sXT[(c+0)*64 + off] = v.x;
        sXT[(c+1)*64 + off] = v.y;
        sXT[(c+2)*64 + off] = v.z;
        sXT[(c+3)*64 + off] = v.w;
    }
    const int tr = tid >> 4, tc = tid & 15;
    const int r0 = tr * 4, c0 = tc * 4;

    #pragma unroll
    for (int m = 0; m < 3; m++) {
        const float* WT   = (m==0) ? WT0 : (m==1) ? WT1 : WT2;
        const float* bias = (m==0) ? b0  : (m==1) ? b1  : b2;
        float*       Y    = (m==0) ? Y0  : (m==1) ? Y1  : Y2;
        __syncthreads();
        #pragma unroll
        for (int it = 0; it < 4; it++) {
            int flat = it*1024 + tid*4;
            *(float4*)&sW[flat] = *(const float4*)&WT[flat];
        }
        __syncthreads();
        float acc[4][4];
        #pragma unroll
        for (int j = 0; j < 4; j++) {
            float bv = bias[c0 + j];
            #pragma unroll
            for (int i = 0; i < 4; i++) acc[i][j] = bv;
        }
        #pragma unroll 8
        for (int k = 0; k < 64; k++) {
            float4 xv = *(const float4*)&sXT[k*64 + 4*((tr + (k>>2)) & 15)];
            float4 wv = *(const float4*)&sW[k*64 + c0];
            float xa[4] = {xv.x, xv.y, xv.z, xv.w};
            float wa[4] = {wv.x, wv.y, wv.z, wv.w};
            #pragma unroll
            for (int i = 0; i < 4; i++)
                #pragma unroll
                for (int j = 0; j < 4; j++) acc[i][j] = fmaf(xa[i], wa[j], acc[i][j]);
        }
        #pragma unroll
        for (int i = 0; i < 4; i++)
            *(float4*)&Y[(row0 + r0 + i)*64 + c0] =
                make_float4(acc[i][0], acc[i][1], acc[i][2], acc[i][3]);
    }
}

// ---------------- 64x64 GEMM with BN-fold input + stats (W_out stage) ------------
template<int STATS, int TRANS>
__global__ __launch_bounds__(256) void k_gemm(
    const float* __restrict__ X, const float* __restrict__ WT,
    const float* __restrict__ ts, const float* __restrict__ tt,
    float* __restrict__ Y, float* __restrict__ part)
{
    __shared__ float sXT[4096];
    __shared__ float sW[4096];
    __shared__ float sRed[16*128];
    const int tid = threadIdx.x;
    const int row0 = blockIdx.x * 64;

    #pragma unroll
    for (int it = 0; it < 4; it++) {
        int flat = it*1024 + tid*4;
        int r = flat >> 6, c = flat & 63;
        float4 v = *(const float4*)&X[(row0 + r)*64 + c];
        if (TRANS) {
            v.x = fmaxf(fmaf(v.x, ts[c],   tt[c]),   0.f);
            v.y = fmaxf(fmaf(v.y, ts[c+1], tt[c+1]), 0.f);
            v.z = fmaxf(fmaf(v.z, ts[c+2], tt[c+2]), 0.f);
            v.w = fmaxf(fmaf(v.w, ts[c+3], tt[c+3]), 0.f);
        }
        int off = 4*(((r>>2) + (c>>2)) & 15) + (r & 3);
        sXT[(c+0)*64 + off] = v.x;
        sXT[(c+1)*64 + off] = v.y;
        sXT[(c+2)*64 + off] = v.z;
        sXT[(c+3)*64 + off] = v.w;
    }
    #pragma unroll
    for (int it = 0; it < 4; it++) {
        int flat = it*1024 + tid*4;
        *(float4*)&sW[flat] = *(const float4*)&WT[flat];
    }
    __syncthreads();

    const int tr = tid >> 4, tc = tid & 15;
    const int r0 = tr * 4, c0 = tc * 4;
    float acc[4][4];
    #pragma unroll
    for (int i = 0; i < 4; i++)
        #pragma unroll
        for (int j = 0; j < 4; j++) acc[i][j] = 0.f;

    #pragma unroll 8
    for (int k = 0; k < 64; k++) {
        float4 xv = *(const float4*)&sXT[k*64 + 4*((tr + (k>>2)) & 15)];
        float4 wv = *(const float4*)&sW[k*64 + c0];
        float xa[4] = {xv.x, xv.y, xv.z, xv.w};
        float wa[4] = {wv.x, wv.y, wv.z, wv.w};
        #pragma unroll
        for (int i = 0; i < 4; i++)
            #pragma unroll
            for (int j = 0; j < 4; j++) acc[i][j] = fmaf(xa[i], wa[j], acc[i][j]);
    }
    float cs[4] = {0,0,0,0}, cq[4] = {0,0,0,0};
    #pragma unroll
    for (int i = 0; i < 4; i++) {
        float4 v4 = make_float4(acc[i][0], acc[i][1], acc[i][2], acc[i][3]);
        *(float4*)&Y[(row0 + r0 + i)*64 + c0] = v4;
        if (STATS) {
            #pragma unroll
            for (int j = 0; j < 4; j++) { cs[j] += acc[i][j]; cq[j] += acc[i][j]*acc[i][j]; }
        }
    }
    if (STATS) {
        #pragma unroll
        for (int j = 0; j < 4; j++) {
            sRed[tr*128 + c0 + j]      = cs[j];
            sRed[tr*128 + 64 + c0 + j] = cq[j];
        }
        __syncthreads();
        if (tid < 128) {
            float p = 0.f;
            #pragma unroll 4
            for (int r = 0; r < 16; r++) p += sRed[r*128 + tid];
            part[tid*PSTR + blockIdx.x] = p;
        }
    }
}

// ---------------- BN stat finalize: one block per column -------------------------
__device__ __forceinline__ void reduce_col(
    const float* __restrict__ part, int c, int coff, int nb, float count,
    const float* __restrict__ gm, const float* __restrict__ bt,
    float* __restrict__ os, float* __restrict__ ot,
    float* ss, float* sqm)
{
    int tid = threadIdx.x;
    float s = 0.f, q = 0.f;
    for (int i = tid; i < nb; i += 256) {
        s += part[c*PSTR + coff + i];
        q += part[(64 + c)*PSTR + coff + i];
    }
    #pragma unroll
    for (int off = 16; off > 0; off >>= 1) {
        s += __shfl_xor_sync(0xffffffffu, s, off);
        q += __shfl_xor_sync(0xffffffffu, q, off);
    }
    if ((tid & 31) == 0) { ss[tid >> 5] = s; sqm[tid >> 5] = q; }
    __syncthreads();
    if (tid == 0) {
        double S = 0.0, Q = 0.0;
        #pragma unroll
        for (int w = 0; w < 8; w++) { S += ss[w]; Q += sqm[w]; }
        double mu  = S / (double)count;
        double var = Q / (double)count - mu * mu;
        double sc  = (double)gm[c] / sqrt(var + 1e-5);
        os[c] = (float)sc;
        ot[c] = (float)((double)bt[c] - mu * sc);
    }
}

__global__ __launch_bounds__(256) void k_reduce(
    const float* __restrict__ part, int nb, int ncols,
    const float* __restrict__ gm, const float* __restrict__ bt,
    float count, float* __restrict__ os, float* __restrict__ ot)
{
    __shared__ float ss[8], sqm[8];
    if (blockIdx.x >= (unsigned)ncols) return;
    reduce_col(part, blockIdx.x, 0, nb, count, gm, bt, os, ot, ss, sqm);
}

// fused: blocks 0..63 -> bn1 (cols 0..1023); blocks 64..66 -> pos (cols 1024..2047)
__global__ __launch_bounds__(256) void k_reduce2(
    const float* __restrict__ part,
    const float* __restrict__ gmA, const float* __restrict__ btA,
    float* __restrict__ osA, float* __restrict__ otA,
    const float* __restrict__ gmB, const float* __restrict__ btB,
    float* __restrict__ osB, float* __restrict__ otB)
{
    __shared__ float ss[8], sqm[8];
    if (blockIdx.x < 64)
        reduce_col(part, blockIdx.x, 0, 1024, (float)NN, gmA, btA, osA, otA, ss, sqm);
    else
        reduce_col(part, blockIdx.x - 64, 1024, 1024, (float)EE, gmB, btB, osB, otB, ss, sqm);
}

// ---------------- edge pass 2: attn_bn1 stats of a = asrc[src]-adst[n]+delta -----
// 16 lanes per node, 4 channels per lane (low register pressure, no spills)
__global__ __launch_bounds__(256) void k_e2(
    const int* __restrict__ src,
    const float* __restrict__ pw2, const float* __restrict__ pb2)
{
    __shared__ float sps[4], spt[4], spw2[192], spb2[64];
    __shared__ float sWr[8*128];
    int tid = threadIdx.x;
    if (tid < 3) { sps[tid]=g_pos_s[tid]; spt[tid]=g_pos_t[tid]; }
    if (tid < 192) spw2[tid] = pw2[tid];
    if (tid < 64) spb2[tid] = pb2[tid];
    __syncthreads();

    int l = tid & 31, lg = tid & 15, c0 = lg * 4, b16 = l & ~15;
    int n = blockIdx.x * 16 + (tid >> 4);

    float4 B = *(const float4*)(g_adst + n*64 + c0);
    float bv[4] = {B.x, B.y, B.z, B.w};
    int s = src[n*16 + lg];

    float wc[4][3], bc[4];
    #pragma unroll
    for (int i = 0; i < 4; i++) {
        int c = c0 + i;
        wc[i][0] = spw2[c*3]; wc[i][1] = spw2[c*3+1]; wc[i][2] = spw2[c*3+2];
        bc[i] = spb2[c];
    }
    float ps0 = sps[0], ps1 = sps[1], ps2 = sps[2];
    float pt0 = spt[0], pt1 = spt[1], pt2 = spt[2];

    float sum[4] = {0,0,0,0}, sq[4] = {0,0,0,0};

    #pragma unroll 4
    for (int k = 0; k < 16; k++) {
        int sidx = __shfl_sync(0xffffffffu, s, b16 + k);
        float4 T = g_t4[n*16 + k];
        float d0 = fmaxf(fmaf(T.x, ps0, pt0), 0.f);
        float d1 = fmaxf(fmaf(T.y, ps1, pt1), 0.f);
        float d2 = fmaxf(fmaf(T.z, ps2, pt2), 0.f);
        float4 A = *(const float4*)(g_asrc + sidx*64 + c0);
        float av[4] = {A.x, A.y, A.z, A.w};
        #pragma unroll
        for (int i = 0; i < 4; i++) {
            float del = fmaf(d0, wc[i][0], fmaf(d1, wc[i][1], fmaf(d2, wc[i][2], bc[i])));
            float a = av[i] - bv[i] + del;
            sum[i] += a; sq[i] += a*a;
        }
    }
    #pragma unroll
    for (int i = 0; i < 4; i++) {
        sum[i] += __shfl_xor_sync(0xffffffffu, sum[i], 16);
        sq[i]  += __shfl_xor_sync(0xffffffffu, sq[i],  16);
    }
    int wp = tid >> 5;
    if (l < 16) {
        #pragma unroll
        for (int i = 0; i < 4; i++) {
            sWr[wp*128 + c0 + i]      = sum[i];
            sWr[wp*128 + 64 + c0 + i] = sq[i];
        }
    }
    __syncthreads();
    if (tid < 128) {
        float p = 0.f;
        for (int w = 0; w < 8; w++) p += sWr[w*128 + tid];
        g_part[tid*PSTR + blockIdx.x] = p;
    }
}

// ---------------- edge pass 3: a2pre = relu(bn1(a)) @ attn_w1^T + b1; stats ------
// 16 lanes per node, 4 channels per lane
__global__ __launch_bounds__(256) void k_e3(
    const int* __restrict__ src,
    const float* __restrict__ pw2, const float* __restrict__ pb2,
    const float* __restrict__ aw1, const float* __restrict__ ab1)
{
    __shared__ float sps[4], spt[4], spw2[192], spb2[64];
    __shared__ float sbs[64], sbt[64];
    __shared__ float sW1[512], sB1[8];
    __shared__ float sWr[8*16];
    int tid = threadIdx.x;
    if (tid < 3) { sps[tid]=g_pos_s[tid]; spt[tid]=g_pos_t[tid]; }
    if (tid < 192) spw2[tid] = pw2[tid];
    if (tid < 64) { spb2[tid]=pb2[tid]; sbs[tid]=g_ab1_s[tid]; sbt[tid]=g_ab1_t[tid]; }
    for (int i=tid;i<512;i+=256) sW1[i]=aw1[i];
    if (tid < 8) sB1[tid]=ab1[tid];
    __syncthreads();

    int l = tid & 31, lg = tid & 15, c0 = lg * 4, b16 = l & ~15;
    int n = blockIdx.x * 16 + (tid >> 4);

    float4 B = *(const float4*)(g_adst + n*64 + c0);
    float bv[4] = {B.x, B.y, B.z, B.w};
    int s = src[n*16 + lg];

    float wc[4][3], bc[4], nbs[4], nbt[4];
    #pragma unroll
    for (int i = 0; i < 4; i++) {
        int c = c0 + i;
        wc[i][0] = spw2[c*3]; wc[i][1] = spw2[c*3+1]; wc[i][2] = spw2[c*3+2];
        bc[i] = spb2[c]; nbs[i] = sbs[c]; nbt[i] = sbt[c];
    }
    float ps0 = sps[0], ps1 = sps[1], ps2 = sps[2];
    float pt0 = spt[0], pt1 = spt[1], pt2 = spt[2];

    float s1a = 0.f, s2a = 0.f;

    for (int k = 0; k < 16; k++) {
        int sidx = __shfl_sync(0xffffffffu, s, b16 + k);
        float4 T = g_t4[n*16 + k];
        float d0 = fmaxf(fmaf(T.x, ps0, pt0), 0.f);
        float d1 = fmaxf(fmaf(T.y, ps1, pt1), 0.f);
        float d2 = fmaxf(fmaf(T.z, ps2, pt2), 0.f);
        float4 A = *(const float4*)(g_asrc + sidx*64 + c0);
        float av[4] = {A.x, A.y, A.z, A.w};
        float p[8];
        #pragma unroll
        for (int j = 0; j < 8; j++) p[j] = 0.f;
        #pragma unroll
        for (int i = 0; i < 4; i++) {
            int c = c0 + i;
            float del = fmaf(d0, wc[i][0], fmaf(d1, wc[i][1], fmaf(d2, wc[i][2], bc[i])));
            float a = av[i] - bv[i] + del;
            float a1 = fmaxf(fmaf(a, nbs[i], nbt[i]), 0.f);
            #pragma unroll
            for (int j = 0; j < 8; j++) p[j] = fmaf(a1, sW1[j*64 + c], p[j]);
        }
        #pragma unroll
        for (int off = 1; off < 16; off <<= 1)
            #pragma unroll
            for (int j = 0; j < 8; j++) p[j] += __shfl_xor_sync(0xffffffffu, p[j], off);
        if (lg < 8) {
            float val = p[lg] + sB1[lg];
            g_a2pre[(n*16 + k)*8 + lg] = val;
            s1a += val; s2a += val*val;
        }
    }
    s1a += __shfl_xor_sync(0xffffffffu, s1a, 16);
    s2a += __shfl_xor_sync(0xffffffffu, s2a, 16);
    int wp = tid >> 5;
    if (l < 8) { sWr[wp*16 + lg] = s1a; sWr[wp*16 + 8 + lg] = s2a; }
    __syncthreads();
    if (tid < 128) {
        float p = 0.f;
        if (tid < 8)                    { for (int w = 0; w < 8; w++) p += sWr[w*16 + tid]; }
        else if (tid >= 64 && tid < 72) { for (int w = 0; w < 8; w++) p += sWr[w*16 + 8 + (tid-64)]; }
        g_part[tid*PSTR + blockIdx.x] = p;
    }
}

// ---------------- edge pass 4: attn_w2 + softmax + weighted aggregation ----------
__global__ __launch_bounds__(256) void k_e4(
    const int* __restrict__ src,
    const float* __restrict__ pw2, const float* __restrict__ pb2,
    const float* __restrict__ aw2, const float* __restrict__ ab2)
{
    __shared__ float sps[4], spt[4], spw2[192], spb2[64];
    __shared__ float s2s[8], s2t[8], saw2[64], sB2[8];
    __shared__ float sAlpha[8][128];
    __shared__ float sD[8][16][4];
    __shared__ int   sSrc[8][16];
    __shared__ float sWr[8*128];
    int tid = threadIdx.x;
    if (tid < 3) { sps[tid]=g_pos_s[tid]; spt[tid]=g_pos_t[tid]; }
    if (tid < 192) spw2[tid] = pw2[tid];
    if (tid < 64) { spb2[tid]=pb2[tid]; saw2[tid]=aw2[tid]; }
    if (tid < 8)  { s2s[tid]=g_ab2_s[tid]; s2t[tid]=g_ab2_t[tid]; sB2[tid]=ab2[tid]; }
    __syncthreads();

    int w = tid>>5, l = tid&31, j = l&7;
    int n = blockIdx.x*8 + w;

    if (l < 16) {
        int e = n*16 + l;
        sSrc[w][l] = src[e];
        float4 T = g_t4[e];
        sD[w][l][0] = fmaxf(fmaf(T.x, sps[0], spt[0]), 0.f);
        sD[w][l][1] = fmaxf(fmaf(T.y, sps[1], spt[1]), 0.f);
        sD[w][l][2] = fmaxf(fmaf(T.z, sps[2], spt[2]), 0.f);
    }

    float v[4];
    #pragma unroll
    for (int r=0;r<4;r++) v[r] = g_a2pre[n*128 + r*32 + l];
    float scj = s2s[j], shj = s2t[j];
    #pragma unroll
    for (int r=0;r<4;r++) v[r] = fmaxf(fmaf(v[r],scj,shj),0.f);

    int b8 = l & ~7;
    float a3[4];
    #pragma unroll
    for (int r=0;r<4;r++){
        float acc = sB2[j];
        #pragma unroll
        for (int j2=0;j2<8;j2++)
            acc = fmaf(saw2[j*8+j2], __shfl_sync(0xffffffffu, v[r], b8+j2), acc);
        a3[r] = acc;
    }
    float m = fmaxf(fmaxf(a3[0],a3[1]),fmaxf(a3[2],a3[3]));
    m = fmaxf(m,__shfl_xor_sync(0xffffffffu,m,8));
    m = fmaxf(m,__shfl_xor_sync(0xffffffffu,m,16));
    float ex[4], se = 0.f;
    #pragma unroll
    for (int r=0;r<4;r++){ ex[r]=__expf(a3[r]-m); se+=ex[r]; }
    se += __shfl_xor_sync(0xffffffffu,se,8);
    se += __shfl_xor_sync(0xffffffffu,se,16);
    float inv = 1.f/se;
    #pragma unroll
    for (int r=0;r<4;r++) sAlpha[w][r*32+l] = ex[r]*inv;
    __syncwarp();

    float wa0=spw2[l*3], wa1=spw2[l*3+1], wa2=spw2[l*3+2], ba=spb2[l];
    float wb0=spw2[(l+32)*3], wb1=spw2[(l+32)*3+1], wb2=spw2[(l+32)*3+2], bb=spb2[l+32];
    float acc0=0.f, acc1=0.f;
    #pragma unroll 4
    for (int el=0; el<16; el++){
        int sidx = sSrc[w][el];
        float d0=sD[w][el][0], d1=sD[w][el][1], d2=sD[w][el][2];
        float al = sAlpha[w][el*8 + j];
        float hw0 = g_hW[sidx*64 + l];
        float hw1 = g_hW[sidx*64 + 32 + l];
        float de0 = fmaf(d0,wa0,fmaf(d1,wa1,fmaf(d2,wa2,ba)));
        float de1 = fmaf(d0,wb0,fmaf(d1,wb1,fmaf(d2,wb2,bb)));
        acc0 = fmaf(al, hw0+de0, acc0);
        acc1 = fmaf(al, hw1+de1, acc1);
    }
    g_out[n*64 + l]      = acc0;
    g_out[n*64 + 32 + l] = acc1;
    sWr[w*128 + l]      = acc0;
    sWr[w*128 + 32 + l] = acc1;
    sWr[w*128 + 64 + l] = acc0*acc0;
    sWr[w*128 + 96 + l] = acc1*acc1;
    __syncthreads();
    if (tid<128){ float p=0.f; for (int ww=0;ww<8;ww++) p+=sWr[ww*128+tid];
                  g_part[tid*PSTR + blockIdx.x]=p; }
}

// ---------------- final: out = relu(bn3(y3) + x) ---------------------------------
__global__ __launch_bounds__(256) void k_final(
    const float* __restrict__ y3, const float* __restrict__ x, float* __restrict__ out)
{
    int i = blockIdx.x*256 + threadIdx.x;
    int cb = (i*4) & 63;
    float4 a  = *(const float4*)(y3 + i*4);
    float4 xv = *(const float4*)(x  + i*4);
    float4 r;
    r.x = fmaxf(fmaf(a.x, g_bn3_s[cb],   g_bn3_t[cb])   + xv.x, 0.f);
    r.y = fmaxf(fmaf(a.y, g_bn3_s[cb+1], g_bn3_t[cb+1]) + xv.y, 0.f);
    r.z = fmaxf(fmaf(a.z, g_bn3_s[cb+2], g_bn3_t[cb+2]) + xv.z, 0.f);
    r.w = fmaxf(fmaf(a.w, g_bn3_s[cb+3], g_bn3_t[cb+3]) + xv.w, 0.f);
    *(float4*)(out + i*4) = r;
}

// ---------------- host ------------------------------------------------------------
extern "C" void kernel_launch(void* const* d_in, const int* in_sizes, int n_in,
                              void* d_out, int out_size)
{
    const float* x          = (const float*)d_in[0];
    const float* pos        = (const float*)d_in[1];
    const int*   ei         = (const int*)  d_in[2];
    const float* W_in       = (const float*)d_in[3];
    const float* W_out      = (const float*)d_in[4];
    const float* pos_w1     = (const float*)d_in[5];
    const float* pos_b1     = (const float*)d_in[6];
    const float* pos_bn_g   = (const float*)d_in[7];
    const float* pos_bn_b   = (const float*)d_in[8];
    const float* pos_w2     = (const float*)d_in[9];
    const float* pos_b2     = (const float*)d_in[10];
    const float* attn_bn1_g = (const float*)d_in[11];
    const float* attn_bn1_b = (const float*)d_in[12];
    const float* attn_w1    = (const float*)d_in[13];
    const float* attn_b1    = (const float*)d_in[14];
    const float* attn_bn2_g = (const float*)d_in[15];
    const float* attn_bn2_b = (const float*)d_in[16];
    const float* attn_w2    = (const float*)d_in[17];
    const float* attn_b2    = (const float*)d_in[18];
    const float* lin_w      = (const float*)d_in[19];
    const float* lin_b      = (const float*)d_in[20];
    const float* src_w      = (const float*)d_in[21];
    const float* src_b      = (const float*)d_in[22];
    const float* dst_w      = (const float*)d_in[23];
    const float* dst_b      = (const float*)d_in[24];
    const float* bn1_g      = (const float*)d_in[25];
    const float* bn1_b      = (const float*)d_in[26];
    const float* bn2_g      = (const float*)d_in[27];
    const float* bn2_b      = (const float*)d_in[28];
    const float* bn3_g      = (const float*)d_in[29];
    const float* bn3_b      = (const float*)d_in[30];
    const int* srcp = ei;  // edge_index row 0

    float *p_y,*p_asrc,*p_adst,*p_hW,*p_out,*p_y3,*p_part,*p_wt;
    float *p_bn1s,*p_bn1t,*p_poss,*p_post,*p_ab1s,*p_ab1t,*p_ab2s,*p_ab2t,*p_bn2s,*p_bn2t,*p_bn3s,*p_bn3t;
    cudaGetSymbolAddress((void**)&p_y,    g_y);
    cudaGetSymbolAddress((void**)&p_asrc, g_asrc);
    cudaGetSymbolAddress((void**)&p_adst, g_adst);
    cudaGetSymbolAddress((void**)&p_hW,   g_hW);
    cudaGetSymbolAddress((void**)&p_out,  g_out);
    cudaGetSymbolAddress((void**)&p_y3,   g_y3);
    cudaGetSymbolAddress((void**)&p_part, g_part);
    cudaGetSymbolAddress((void**)&p_wt,   g_WT5);
    cudaGetSymbolAddress((void**)&p_bn1s, g_bn1_s); cudaGetSymbolAddress((void**)&p_bn1t, g_bn1_t);
    cudaGetSymbolAddress((void**)&p_poss, g_pos_s); cudaGetSymbolAddress((void**)&p_post, g_pos_t);
    cudaGetSymbolAddress((void**)&p_ab1s, g_ab1_s); cudaGetSymbolAddress((void**)&p_ab1t, g_ab1_t);
    cudaGetSymbolAddress((void**)&p_ab2s, g_ab2_s); cudaGetSymbolAddress((void**)&p_ab2t, g_ab2_t);
    cudaGetSymbolAddress((void**)&p_bn2s, g_bn2_s); cudaGetSymbolAddress((void**)&p_bn2t, g_bn2_t);
    cudaGetSymbolAddress((void**)&p_bn3s, g_bn3_s); cudaGetSymbolAddress((void**)&p_bn3t, g_bn3_t);

    // 0) pre-transpose weights (W_in, src_w, dst_w, lin_w, W_out)
    k_tw<<<5,256>>>(W_in, src_w, dst_w, lin_w, W_out, p_wt);
    // 1) fused: GEMM1 (bn1 partials) + pos-MLP edge pass (pos partials)
    k_front<<<2048,256>>>(x, p_wt, p_y, p_part, srcp, pos, pos_w1, pos_b1);
    k_reduce2<<<67,256>>>(p_part, bn1_g, bn1_b, p_bn1s, p_bn1t,
                          pos_bn_g, pos_bn_b, p_poss, p_post);
    // 2) fused triple GEMM on h = relu(bn1(y))
    k_gemm3<<<1024,256>>>(p_y, p_wt + 4096, p_wt + 2*4096, p_wt + 3*4096,
                          src_b, dst_b, lin_b, p_bn1s, p_bn1t, p_asrc, p_adst, p_hW);
    // 3) attn_bn1 stats (16 lanes/node, grid = NN/16)
    k_e2<<<4096,256>>>(srcp, pos_w2, pos_b2);
    k_reduce<<<64,256>>>(p_part, 4096, 64, attn_bn1_g, attn_bn1_b, (float)EE, p_ab1s, p_ab1t);
    // 4) a2pre + attn_bn2 stats (16 lanes/node, grid = NN/16)
    k_e3<<<4096,256>>>(srcp, pos_w2, pos_b2, attn_w1, attn_b1);
    k_reduce<<<64,256>>>(p_part, 4096, 8, attn_bn2_g, attn_bn2_b, (float)EE, p_ab2s, p_ab2t);
    // 5) softmax + aggregate (+ bn2 stats)
    k_e4<<<8192,256>>>(srcp, pos_w2, pos_b2, attn_w2, attn_b2);
    k_reduce<<<64,256>>>(p_part, 8192, 64, bn2_g, bn2_b, (float)NN, p_bn2s, p_bn2t);
    // 6) y3 = relu(bn2(out)) @ W_out^T (+ bn3 stats)
    k_gemm<1,1><<<1024,256>>>(p_out, p_wt + 4*4096, p_bn2s, p_bn2t, p_y3, p_part);
    k_reduce<<<64,256>>>(p_part, 1024, 64, bn3_g, bn3_b, (float)NN, p_bn3s, p_bn3t);
    // 7) final residual + relu
    k_final<<<4096,256>>>(p_y3, x, (float*)d_out);
}

// round 14
// speedup vs baseline: 1.0498x; 1.0498x over previous
#include <cuda_runtime.h>

#define NN 65536
#define CC 64
#define KNN 16
#define EE (NN*KNN)
#define C8 8
#define PSTR 8192

// ---------------- scratch (device globals; no allocation allowed) ----------------
__device__ float g_y[NN*CC];      // x @ W_in^T (pre-BN)
__device__ float g_asrc[NN*CC];   // h @ src_w^T + src_b
__device__ float g_adst[NN*CC];   // h @ dst_w^T + dst_b
__device__ float g_hW[NN*CC];     // h @ lin_w^T + lin_b
__device__ float g_out[NN*CC];    // aggregated messages (pre-BN2)
__device__ float g_y3[NN*CC];     // h2 @ W_out^T (pre-BN3)
__device__ float g_a2pre[EE*C8];  // attn inner activations (pre-BN attn2)
__device__ float4 g_t4[EE];       // pre-BN pos-MLP output per edge
__device__ float g_part[128*PSTR];// transposed block partials: [stat][block]
__device__ float g_WT5[5*4096];   // pre-transposed weights: WT[k][j] per matrix

__device__ float g_bn1_s[CC], g_bn1_t[CC];
__device__ float g_pos_s[4],  g_pos_t[4];
__device__ float g_ab1_s[CC], g_ab1_t[CC];
__device__ float g_ab2_s[C8], g_ab2_t[C8];
__device__ float g_bn2_s[CC], g_bn2_t[CC];
__device__ float g_bn3_s[CC], g_bn3_t[CC];

// ---------------- weight pre-transpose: WT[k][j] = W[j][k], 5 matrices -----------
__global__ __launch_bounds__(256) void k_tw(
    const float* __restrict__ W0, const float* __restrict__ W1,
    const float* __restrict__ W2, const float* __restrict__ W3,
    const float* __restrict__ W4, float* __restrict__ out)
{
    const float* W = (blockIdx.x==0)?W0:(blockIdx.x==1)?W1:(blockIdx.x==2)?W2:(blockIdx.x==3)?W3:W4;
    float* o = out + blockIdx.x*4096;
    __shared__ float s[64*65];
    int tid = threadIdx.x;
    #pragma unroll
    for (int it = 0; it < 4; it++) {
        int f = it*1024 + tid*4;
        int j = f >> 6, k = f & 63;
        float4 v = *(const float4*)&W[j*64 + k];
        s[j*65+k]=v.x; s[j*65+k+1]=v.y; s[j*65+k+2]=v.z; s[j*65+k+3]=v.w;
    }
    __syncthreads();
    #pragma unroll
    for (int it = 0; it < 4; it++) {
        int f = it*1024 + tid*4;
        int k = f >> 6, j = f & 63;
        float4 v = make_float4(s[(j+0)*65+k], s[(j+1)*65+k], s[(j+2)*65+k], s[(j+3)*65+k]);
        *(float4*)&o[k*64 + j] = v;
    }
}

// swizzled X-tile store offset: element (c, r) lives at float index
//   (c)*64 + 4*((r/4 + c/4) & 15) + (r&3)

// ---------------- fused front: blocks 0..1023 GEMM1 (+bn1 partials),
//                  blocks 1024..2047 pos-MLP edge pass (+pos partials) ------------
__global__ __launch_bounds__(256) void k_front(
    const float* __restrict__ X, const float* __restrict__ WT,
    float* __restrict__ Y, float* __restrict__ part,
    const int* __restrict__ src, const float* __restrict__ pos,
    const float* __restrict__ pw1, const float* __restrict__ pb1)
{
    __shared__ float sXT[4096];
    __shared__ float sW[4096];
    __shared__ float sRed[16*128];
    const int tid = threadIdx.x;

    if (blockIdx.x < 1024) {
        const int row0 = blockIdx.x * 64;
        #pragma unroll
        for (int it = 0; it < 4; it++) {
            int flat = it*1024 + tid*4;
            int r = flat >> 6, c = flat & 63;
            float4 v = *(const float4*)&X[(row0 + r)*64 + c];
            int off = 4*(((r>>2) + (c>>2)) & 15) + (r & 3);
            sXT[(c+0)*64 + off] = v.x;
            sXT[(c+1)*64 + off] = v.y;
            sXT[(c+2)*64 + off] = v.z;
            sXT[(c+3)*64 + off] = v.w;
        }
        #pragma unroll
        for (int it = 0; it < 4; it++) {
            int flat = it*1024 + tid*4;
            *(float4*)&sW[flat] = *(const float4*)&WT[flat];
        }
        __syncthreads();

        const int tr = tid >> 4, tc = tid & 15;
        const int r0 = tr * 4, c0 = tc * 4;
        float acc[4][4];
        #pragma unroll
        for (int i = 0; i < 4; i++)
            #pragma unroll
            for (int j = 0; j < 4; j++) acc[i][j] = 0.f;

        #pragma unroll 8
        for (int k = 0; k < 64; k++) {
            float4 xv = *(const float4*)&sXT[k*64 + 4*((tr + (k>>2)) & 15)];
            float4 wv = *(const float4*)&sW[k*64 + c0];
            float xa[4] = {xv.x, xv.y, xv.z, xv.w};
            float wa[4] = {wv.x, wv.y, wv.z, wv.w};
            #pragma unroll
            for (int i = 0; i < 4; i++)
                #pragma unroll
                for (int j = 0; j < 4; j++) acc[i][j] = fmaf(xa[i], wa[j], acc[i][j]);
        }
        float cs[4] = {0,0,0,0}, cq[4] = {0,0,0,0};
        #pragma unroll
        for (int i = 0; i < 4; i++) {
            float4 v4 = make_float4(acc[i][0], acc[i][1], acc[i][2], acc[i][3]);
            *(float4*)&Y[(row0 + r0 + i)*64 + c0] = v4;
            #pragma unroll
            for (int j = 0; j < 4; j++) { cs[j] += acc[i][j]; cq[j] += acc[i][j]*acc[i][j]; }
        }
        #pragma unroll
        for (int j = 0; j < 4; j++) {
            sRed[tr*128 + c0 + j]      = cs[j];
            sRed[tr*128 + 64 + c0 + j] = cq[j];
        }
        __syncthreads();
        if (tid < 128) {
            float p = 0.f;
            #pragma unroll 4
            for (int r = 0; r < 16; r++) p += sRed[r*128 + tid];
            part[tid*PSTR + blockIdx.x] = p;
        }
    } else {
        const int bid = blockIdx.x - 1024;
        float w0=pw1[0],w1=pw1[1],w2=pw1[2],w3=pw1[3],w4=pw1[4],w5=pw1[5],w6=pw1[6],w7=pw1[7],w8=pw1[8];
        float b0=pb1[0],b1=pb1[1],b2=pb1[2];
        float s0=0,s1=0,s2=0,q0=0,q1=0,q2=0;
        int stride = 1024 * 256;
        for (int e = bid*256 + tid; e < EE; e += stride) {
            int sp = src[e]*3, np = (e >> 4)*3;
            float rx = pos[sp]-pos[np], ry = pos[sp+1]-pos[np+1], rz = pos[sp+2]-pos[np+2];
            float t0 = fmaf(w0,rx,fmaf(w1,ry,fmaf(w2,rz,b0)));
            float t1 = fmaf(w3,rx,fmaf(w4,ry,fmaf(w5,rz,b1)));
            float t2 = fmaf(w6,rx,fmaf(w7,ry,fmaf(w8,rz,b2)));
            g_t4[e] = make_float4(t0, t1, t2, 0.f);
            s0+=t0; s1+=t1; s2+=t2; q0+=t0*t0; q1+=t1*t1; q2+=t2*t2;
        }
        #pragma unroll
        for (int off=16; off>0; off>>=1) {
            s0+=__shfl_xor_sync(0xffffffffu,s0,off); s1+=__shfl_xor_sync(0xffffffffu,s1,off);
            s2+=__shfl_xor_sync(0xffffffffu,s2,off); q0+=__shfl_xor_sync(0xffffffffu,q0,off);
            q1+=__shfl_xor_sync(0xffffffffu,q1,off); q2+=__shfl_xor_sync(0xffffffffu,q2,off);
        }
        int wp = tid>>5;
        if ((tid&31)==0){ sRed[wp*8+0]=s0; sRed[wp*8+1]=s1; sRed[wp*8+2]=s2;
                          sRed[wp*8+4]=q0; sRed[wp*8+5]=q1; sRed[wp*8+6]=q2; }
        __syncthreads();
        if (tid < 128) {
            float p = 0.f;
            if (tid < 3)                    { for (int w=0;w<8;w++) p += sRed[w*8+tid]; }
            else if (tid >= 64 && tid < 67) { for (int w=0;w<8;w++) p += sRed[w*8+4+(tid-64)]; }
            g_part[tid*PSTR + 1024 + bid] = p;
        }
    }
}

// ---------------- fused triple GEMM: Y_m = relu(bn(X)) @ W_m^T + b_m -------------
__global__ __launch_bounds__(256) void k_gemm3(
    const float* __restrict__ X,
    const float* __restrict__ WT0, const float* __restrict__ WT1, const float* __restrict__ WT2,
    const float* __restrict__ b0, const float* __restrict__ b1, const float* __restrict__ b2,
    const float* __restrict__ ts, const float* __restrict__ tt,
    float* __restrict__ Y0, float* __restrict__ Y1, float* __restrict__ Y2)
{
    __shared__ float sXT[4096];
    __shared__ float sW[4096];
    const int tid = threadIdx.x;
    const int row0 = blockIdx.x * 64;

    #pragma unroll
    for (int it = 0; it < 4; it++) {
        int flat = it*1024 + tid*4;
        int r = flat >> 6, c = flat & 63;
        float4 v = *(const float4*)&X[(row0 + r)*64 + c];
        v.x = fmaxf(fmaf(v.x, ts[c],   tt[c]),   0.f);
        v.y = fmaxf(fmaf(v.y, ts[c+1], tt[c+1]), 0.f);
        v.z = fmaxf(fmaf(v.z, ts[c+2], tt[c+2]), 0.f);
        v.w = fmaxf(fmaf(v.w, ts[c+3], tt[c+3]), 0.f);
        int off = 4*(((r>>2) + (c>>2)) & 15) + (r & 3);
        sXT[(c+0)*64 + off] = v.x;
        sXT[(c+1)*64 + off] = v.y;
        sXT[(c+2)*64 + off] = v.z;
        sXT[(c+3)*64 + off] = v.w;
    }
    const int tr = tid >> 4, tc = tid & 15;
    const int r0 = tr * 4, c0 = tc * 4;

    #pragma unroll
    for (int m = 0; m < 3; m++) {
        const float* WT   = (m==0) ? WT0 : (m==1) ? WT1 : WT2;
        const float* bias = (m==0) ? b0  : (m==1) ? b1  : b2;
        float*       Y    = (m==0) ? Y0  : (m==1) ? Y1  : Y2;
        __syncthreads();
        #pragma unroll
        for (int it = 0; it < 4; it++) {
            int flat = it*1024 + tid*4;
            *(float4*)&sW[flat] = *(const float4*)&WT[flat];
        }
        __syncthreads();
        float acc[4][4];
        #pragma unroll
        for (int j = 0; j < 4; j++) {
            float bv = bias[c0 + j];
            #pragma unroll
            for (int i = 0; i < 4; i++) acc[i][j] = bv;
        }
        #pragma unroll 8
        for (int k = 0; k < 64; k++) {
            float4 xv = *(const float4*)&sXT[k*64 + 4*((tr + (k>>2)) & 15)];
            float4 wv = *(const float4*)&sW[k*64 + c0];
            float xa[4] = {xv.x, xv.y, xv.z, xv.w};
            float wa[4] = {wv.x, wv.y, wv.z, wv.w};
            #pragma unroll
            for (int i = 0; i < 4; i++)
                #pragma unroll
                for (int j = 0; j < 4; j++) acc[i][j] = fmaf(xa[i], wa[j], acc[i][j]);
        }
        #pragma unroll
        for (int i = 0; i < 4; i++)
            *(float4*)&Y[(row0 + r0 + i)*64 + c0] =
                make_float4(acc[i][0], acc[i][1], acc[i][2], acc[i][3]);
    }
}

// ---------------- 64x64 GEMM with BN-fold input + stats (W_out stage) ------------
template<int STATS, int TRANS>
__global__ __launch_bounds__(256) void k_gemm(
    const float* __restrict__ X, const float* __restrict__ WT,
    const float* __restrict__ ts, const float* __restrict__ tt,
    float* __restrict__ Y, float* __restrict__ part)
{
    __shared__ float sXT[4096];
    __shared__ float sW[4096];
    __shared__ float sRed[16*128];
    const int tid = threadIdx.x;
    const int row0 = blockIdx.x * 64;

    #pragma unroll
    for (int it = 0; it < 4; it++) {
        int flat = it*1024 + tid*4;
        int r = flat >> 6, c = flat & 63;
        float4 v = *(const float4*)&X[(row0 + r)*64 + c];
        if (TRANS) {
            v.x = fmaxf(fmaf(v.x, ts[c],   tt[c]),   0.f);
            v.y = fmaxf(fmaf(v.y, ts[c+1], tt[c+1]), 0.f);
            v.z = fmaxf(fmaf(v.z, ts[c+2], tt[c+2]), 0.f);
            v.w = fmaxf(fmaf(v.w, ts[c+3], tt[c+3]), 0.f);
        }
        int off = 4*(((r>>2) + (c>>2)) & 15) + (r & 3);
        sXT[(c+0)*64 + off] = v.x;
        sXT[(c+1)*64 + off] = v.y;
        sXT[(c+2)*64 + off] = v.z;
        sXT[(c+3)*64 + off] = v.w;
    }
    #pragma unroll
    for (int it = 0; it < 4; it++) {
        int flat = it*1024 + tid*4;
        *(float4*)&sW[flat] = *(const float4*)&WT[flat];
    }
    __syncthreads();

    const int tr = tid >> 4, tc = tid & 15;
    const int r0 = tr * 4, c0 = tc * 4;
    float acc[4][4];
    #pragma unroll
    for (int i = 0; i < 4; i++)
        #pragma unroll
        for (int j = 0; j < 4; j++) acc[i][j] = 0.f;

    #pragma unroll 8
    for (int k = 0; k < 64; k++) {
        float4 xv = *(const float4*)&sXT[k*64 + 4*((tr + (k>>2)) & 15)];
        float4 wv = *(const float4*)&sW[k*64 + c0];
        float xa[4] = {xv.x, xv.y, xv.z, xv.w};
        float wa[4] = {wv.x, wv.y, wv.z, wv.w};
        #pragma unroll
        for (int i = 0; i < 4; i++)
            #pragma unroll
            for (int j = 0; j < 4; j++) acc[i][j] = fmaf(xa[i], wa[j], acc[i][j]);
    }
    float cs[4] = {0,0,0,0}, cq[4] = {0,0,0,0};
    #pragma unroll
    for (int i = 0; i < 4; i++) {
        float4 v4 = make_float4(acc[i][0], acc[i][1], acc[i][2], acc[i][3]);
        *(float4*)&Y[(row0 + r0 + i)*64 + c0] = v4;
        if (STATS) {
            #pragma unroll
            for (int j = 0; j < 4; j++) { cs[j] += acc[i][j]; cq[j] += acc[i][j]*acc[i][j]; }
        }
    }
    if (STATS) {
        #pragma unroll
        for (int j = 0; j < 4; j++) {
            sRed[tr*128 + c0 + j]      = cs[j];
            sRed[tr*128 + 64 + c0 + j] = cq[j];
        }
        __syncthreads();
        if (tid < 128) {
            float p = 0.f;
            #pragma unroll 4
            for (int r = 0; r < 16; r++) p += sRed[r*128 + tid];
            part[tid*PSTR + blockIdx.x] = p;
        }
    }
}

// ---------------- BN stat finalize: one block per column -------------------------
__device__ __forceinline__ void reduce_col(
    const float* __restrict__ part, int c, int coff, int nb, float count,
    const float* __restrict__ gm, const float* __restrict__ bt,
    float* __restrict__ os, float* __restrict__ ot,
    float* ss, float* sqm)
{
    int tid = threadIdx.x;
    float s = 0.f, q = 0.f;
    for (int i = tid; i < nb; i += 256) {
        s += part[c*PSTR + coff + i];
        q += part[(64 + c)*PSTR + coff + i];
    }
    #pragma unroll
    for (int off = 16; off > 0; off >>= 1) {
        s += __shfl_xor_sync(0xffffffffu, s, off);
        q += __shfl_xor_sync(0xffffffffu, q, off);
    }
    if ((tid & 31) == 0) { ss[tid >> 5] = s; sqm[tid >> 5] = q; }
    __syncthreads();
    if (tid == 0) {
        double S = 0.0, Q = 0.0;
        #pragma unroll
        for (int w = 0; w < 8; w++) { S += ss[w]; Q += sqm[w]; }
        double mu  = S / (double)count;
        double var = Q / (double)count - mu * mu;
        double sc  = (double)gm[c] / sqrt(var + 1e-5);
        os[c] = (float)sc;
        ot[c] = (float)((double)bt[c] - mu * sc);
    }
}

__global__ __launch_bounds__(256) void k_reduce(
    const float* __restrict__ part, int nb, int ncols,
    const float* __restrict__ gm, const float* __restrict__ bt,
    float count, float* __restrict__ os, float* __restrict__ ot)
{
    __shared__ float ss[8], sqm[8];
    if (blockIdx.x >= (unsigned)ncols) return;
    reduce_col(part, blockIdx.x, 0, nb, count, gm, bt, os, ot, ss, sqm);
}

// fused: blocks 0..63 -> bn1 (cols 0..1023); blocks 64..66 -> pos (cols 1024..2047)
__global__ __launch_bounds__(256) void k_reduce2(
    const float* __restrict__ part,
    const float* __restrict__ gmA, const float* __restrict__ btA,
    float* __restrict__ osA, float* __restrict__ otA,
    const float* __restrict__ gmB, const float* __restrict__ btB,
    float* __restrict__ osB, float* __restrict__ otB)
{
    __shared__ float ss[8], sqm[8];
    if (blockIdx.x < 64)
        reduce_col(part, blockIdx.x, 0, 1024, (float)NN, gmA, btA, osA, otA, ss, sqm);
    else
        reduce_col(part, blockIdx.x - 64, 1024, 1024, (float)EE, gmB, btB, osB, otB, ss, sqm);
}

// ---------------- edge pass 2: attn_bn1 stats of a = asrc[src]-adst[n]+delta -----
// 16 lanes per node, 4 channels per lane; d computed once per edge, shuffled
__global__ __launch_bounds__(256) void k_e2(
    const int* __restrict__ src,
    const float* __restrict__ pw2, const float* __restrict__ pb2)
{
    __shared__ float sps[4], spt[4], spw2[192], spb2[64];
    __shared__ float sWr[8*128];
    int tid = threadIdx.x;
    if (tid < 3) { sps[tid]=g_pos_s[tid]; spt[tid]=g_pos_t[tid]; }
    if (tid < 192) spw2[tid] = pw2[tid];
    if (tid < 64) spb2[tid] = pb2[tid];
    __syncthreads();

    int l = tid & 31, lg = tid & 15, c0 = lg * 4, b16 = l & ~15;
    int n = blockIdx.x * 16 + (tid >> 4);

    float4 B = *(const float4*)(g_adst + n*64 + c0);
    float bv[4] = {B.x, B.y, B.z, B.w};
    int s = src[n*16 + lg];

    // lane lg owns edge lg: load its T once, compute d once
    float dx, dy, dz;
    {
        float4 T = g_t4[n*16 + lg];
        dx = fmaxf(fmaf(T.x, sps[0], spt[0]), 0.f);
        dy = fmaxf(fmaf(T.y, sps[1], spt[1]), 0.f);
        dz = fmaxf(fmaf(T.z, sps[2], spt[2]), 0.f);
    }

    float wc[4][3], bc[4];
    #pragma unroll
    for (int i = 0; i < 4; i++) {
        int c = c0 + i;
        wc[i][0] = spw2[c*3]; wc[i][1] = spw2[c*3+1]; wc[i][2] = spw2[c*3+2];
        bc[i] = spb2[c];
    }

    float sum[4] = {0,0,0,0}, sq[4] = {0,0,0,0};

    #pragma unroll 4
    for (int k = 0; k < 16; k++) {
        int sidx = __shfl_sync(0xffffffffu, s, b16 + k);
        float d0 = __shfl_sync(0xffffffffu, dx, b16 + k);
        float d1 = __shfl_sync(0xffffffffu, dy, b16 + k);
        float d2 = __shfl_sync(0xffffffffu, dz, b16 + k);
        float4 A = *(const float4*)(g_asrc + sidx*64 + c0);
        float av[4] = {A.x, A.y, A.z, A.w};
        #pragma unroll
        for (int i = 0; i < 4; i++) {
            float del = fmaf(d0, wc[i][0], fmaf(d1, wc[i][1], fmaf(d2, wc[i][2], bc[i])));
            float a = av[i] - bv[i] + del;
            sum[i] += a; sq[i] += a*a;
        }
    }
    #pragma unroll
    for (int i = 0; i < 4; i++) {
        sum[i] += __shfl_xor_sync(0xffffffffu, sum[i], 16);
        sq[i]  += __shfl_xor_sync(0xffffffffu, sq[i],  16);
    }
    int wp = tid >> 5;
    if (l < 16) {
        #pragma unroll
        for (int i = 0; i < 4; i++) {
            sWr[wp*128 + c0 + i]      = sum[i];
            sWr[wp*128 + 64 + c0 + i] = sq[i];
        }
    }
    __syncthreads();
    if (tid < 128) {
        float p = 0.f;
        for (int w = 0; w < 8; w++) p += sWr[w*128 + tid];
        g_part[tid*PSTR + blockIdx.x] = p;
    }
}

// ---------------- edge pass 3: a2pre = relu(bn1(a)) @ attn_w1^T + b1; stats ------
// 16 lanes per node, 4 channels per lane; d computed once per edge, shuffled
__global__ __launch_bounds__(256) void k_e3(
    const int* __restrict__ src,
    const float* __restrict__ pw2, const float* __restrict__ pb2,
    const float* __restrict__ aw1, const float* __restrict__ ab1)
{
    __shared__ float sps[4], spt[4], spw2[192], spb2[64];
    __shared__ float sbs[64], sbt[64];
    __shared__ float sW1[512], sB1[8];
    __shared__ float sWr[8*16];
    int tid = threadIdx.x;
    if (tid < 3) { sps[tid]=g_pos_s[tid]; spt[tid]=g_pos_t[tid]; }
    if (tid < 192) spw2[tid] = pw2[tid];
    if (tid < 64) { spb2[tid]=pb2[tid]; sbs[tid]=g_ab1_s[tid]; sbt[tid]=g_ab1_t[tid]; }
    for (int i=tid;i<512;i+=256) sW1[i]=aw1[i];
    if (tid < 8) sB1[tid]=ab1[tid];
    __syncthreads();

    int l = tid & 31, lg = tid & 15, c0 = lg * 4, b16 = l & ~15;
    int n = blockIdx.x * 16 + (tid >> 4);

    float4 B = *(const float4*)(g_adst + n*64 + c0);
    float bv[4] = {B.x, B.y, B.z, B.w};
    int s = src[n*16 + lg];

    float dx, dy, dz;
    {
        float4 T = g_t4[n*16 + lg];
        dx = fmaxf(fmaf(T.x, sps[0], spt[0]), 0.f);
        dy = fmaxf(fmaf(T.y, sps[1], spt[1]), 0.f);
        dz = fmaxf(fmaf(T.z, sps[2], spt[2]), 0.f);
    }

    float wc[4][3], bc[4], nbs[4], nbt[4];
    #pragma unroll
    for (int i = 0; i < 4; i++) {
        int c = c0 + i;
        wc[i][0] = spw2[c*3]; wc[i][1] = spw2[c*3+1]; wc[i][2] = spw2[c*3+2];
        bc[i] = spb2[c]; nbs[i] = sbs[c]; nbt[i] = sbt[c];
    }

    float s1a = 0.f, s2a = 0.f;

    for (int k = 0; k < 16; k++) {
        int sidx = __shfl_sync(0xffffffffu, s, b16 + k);
        float d0 = __shfl_sync(0xffffffffu, dx, b16 + k);
        float d1 = __shfl_sync(0xffffffffu, dy, b16 + k);
        float d2 = __shfl_sync(0xffffffffu, dz, b16 + k);
        float4 A = *(const float4*)(g_asrc + sidx*64 + c0);
        float av[4] = {A.x, A.y, A.z, A.w};
        float p[8];
        #pragma unroll
        for (int j = 0; j < 8; j++) p[j] = 0.f;
        #pragma unroll
        for (int i = 0; i < 4; i++) {
            int c = c0 + i;
            float del = fmaf(d0, wc[i][0], fmaf(d1, wc[i][1], fmaf(d2, wc[i][2], bc[i])));
            float a = av[i] - bv[i] + del;
            float a1 = fmaxf(fmaf(a, nbs[i], nbt[i]), 0.f);
            #pragma unroll
            for (int j = 0; j < 8; j++) p[j] = fmaf(a1, sW1[j*64 + c], p[j]);
        }
        #pragma unroll
        for (int off = 1; off < 16; off <<= 1)
            #pragma unroll
            for (int j = 0; j < 8; j++) p[j] += __shfl_xor_sync(0xffffffffu, p[j], off);
        if (lg < 8) {
            float val = p[lg] + sB1[lg];
            g_a2pre[(n*16 + k)*8 + lg] = val;
            s1a += val; s2a += val*val;
        }
    }
    s1a += __shfl_xor_sync(0xffffffffu, s1a, 16);
    s2a += __shfl_xor_sync(0xffffffffu, s2a, 16);
    int wp = tid >> 5;
    if (l < 8) { sWr[wp*16 + lg] = s1a; sWr[wp*16 + 8 + lg] = s2a; }
    __syncthreads();
    if (tid < 128) {
        float p = 0.f;
        if (tid < 8)                    { for (int w = 0; w < 8; w++) p += sWr[w*16 + tid]; }
        else if (tid >= 64 && tid < 72) { for (int w = 0; w < 8; w++) p += sWr[w*16 + 8 + (tid-64)]; }
        g_part[tid*PSTR + blockIdx.x] = p;
    }
}

// ---------------- edge pass 4: attn_w2 + softmax + weighted aggregation ----------
__global__ __launch_bounds__(256) void k_e4(
    const int* __restrict__ src,
    const float* __restrict__ pw2, const float* __restrict__ pb2,
    const float* __restrict__ aw2, const float* __restrict__ ab2)
{
    __shared__ float sps[4], spt[4], spw2[192], spb2[64];
    __shared__ float s2s[8], s2t[8], saw2[64], sB2[8];
    __shared__ float sAlpha[8][128];
    __shared__ float sD[8][16][4];
    __shared__ int   sSrc[8][16];
    __shared__ float sWr[8*128];
    int tid = threadIdx.x;
    if (tid < 3) { sps[tid]=g_pos_s[tid]; spt[tid]=g_pos_t[tid]; }
    if (tid < 192) spw2[tid] = pw2[tid];
    if (tid < 64) { spb2[tid]=pb2[tid]; saw2[tid]=aw2[tid]; }
    if (tid < 8)  { s2s[tid]=g_ab2_s[tid]; s2t[tid]=g_ab2_t[tid]; sB2[tid]=ab2[tid]; }
    __syncthreads();

    int w = tid>>5, l = tid&31, j = l&7;
    int n = blockIdx.x*8 + w;

    if (l < 16) {
        int e = n*16 + l;
        sSrc[w][l] = src[e];
        float4 T = g_t4[e];
        sD[w][l][0] = fmaxf(fmaf(T.x, sps[0], spt[0]), 0.f);
        sD[w][l][1] = fmaxf(fmaf(T.y, sps[1], spt[1]), 0.f);
        sD[w][l][2] = fmaxf(fmaf(T.z, sps[2], spt[2]), 0.f);
    }

    float v[4];
    #pragma unroll
    for (int r=0;r<4;r++) v[r] = g_a2pre[n*128 + r*32 + l];
    float scj = s2s[j], shj = s2t[j];
    #pragma unroll
    for (int r=0;r<4;r++) v[r] = fmaxf(fmaf(v[r],scj,shj),0.f);

    int b8 = l & ~7;
    float a3[4];
    #pragma unroll
    for (int r=0;r<4;r++){
        float acc = sB2[j];
        #pragma unroll
        for (int j2=0;j2<8;j2++)
            acc = fmaf(saw2[j*8+j2], __shfl_sync(0xffffffffu, v[r], b8+j2), acc);
        a3[r] = acc;
    }
    float m = fmaxf(fmaxf(a3[0],a3[1]),fmaxf(a3[2],a3[3]));
    m = fmaxf(m,__shfl_xor_sync(0xffffffffu,m,8));
    m = fmaxf(m,__shfl_xor_sync(0xffffffffu,m,16));
    float ex[4], se = 0.f;
    #pragma unroll
    for (int r=0;r<4;r++){ ex[r]=__expf(a3[r]-m); se+=ex[r]; }
    se += __shfl_xor_sync(0xffffffffu,se,8);
    se += __shfl_xor_sync(0xffffffffu,se,16);
    float inv = 1.f/se;
    #pragma unroll
    for (int r=0;r<4;r++) sAlpha[w][r*32+l] = ex[r]*inv;
    __syncwarp();

    float wa0=spw2[l*3], wa1=spw2[l*3+1], wa2=spw2[l*3+2], ba=spb2[l];
    float wb0=spw2[(l+32)*3], wb1=spw2[(l+32)*3+1], wb2=spw2[(l+32)*3+2], bb=spb2[l+32];
    float acc0=0.f, acc1=0.f;
    #pragma unroll 4
    for (int el=0; el<16; el++){
        int sidx = sSrc[w][el];
        float d0=sD[w][el][0], d1=sD[w][el][1], d2=sD[w][el][2];
        float al = sAlpha[w][el*8 + j];
        float hw0 = g_hW[sidx*64 + l];
        float hw1 = g_hW[sidx*64 + 32 + l];
        float de0 = fmaf(d0,wa0,fmaf(d1,wa1,fmaf(d2,wa2,ba)));
        float de1 = fmaf(d0,wb0,fmaf(d1,wb1,fmaf(d2,wb2,bb)));
        acc0 = fmaf(al, hw0+de0, acc0);
        acc1 = fmaf(al, hw1+de1, acc1);
    }
    g_out[n*64 + l]      = acc0;
    g_out[n*64 + 32 + l] = acc1;
    sWr[w*128 + l]      = acc0;
    sWr[w*128 + 32 + l] = acc1;
    sWr[w*128 + 64 + l] = acc0*acc0;
    sWr[w*128 + 96 + l] = acc1*acc1;
    __syncthreads();
    if (tid<128){ float p=0.f; for (int ww=0;ww<8;ww++) p+=sWr[ww*128+tid];
                  g_part[tid*PSTR + blockIdx.x]=p; }
}

// ---------------- final: out = relu(bn3(y3) + x) ---------------------------------
__global__ __launch_bounds__(256) void k_final(
    const float* __restrict__ y3, const float* __restrict__ x, float* __restrict__ out)
{
    int i = blockIdx.x*256 + threadIdx.x;
    int cb = (i*4) & 63;
    float4 a  = *(const float4*)(y3 + i*4);
    float4 xv = *(const float4*)(x  + i*4);
    float4 r;
    r.x = fmaxf(fmaf(a.x, g_bn3_s[cb],   g_bn3_t[cb])   + xv.x, 0.f);
    r.y = fmaxf(fmaf(a.y, g_bn3_s[cb+1], g_bn3_t[cb+1]) + xv.y, 0.f);
    r.z = fmaxf(fmaf(a.z, g_bn3_s[cb+2], g_bn3_t[cb+2]) + xv.z, 0.f);
    r.w = fmaxf(fmaf(a.w, g_bn3_s[cb+3], g_bn3_t[cb+3]) + xv.w, 0.f);
    *(float4*)(out + i*4) = r;
}

// ---------------- host ------------------------------------------------------------
extern "C" void kernel_launch(void* const* d_in, const int* in_sizes, int n_in,
                              void* d_out, int out_size)
{
    const float* x          = (const float*)d_in[0];
    const float* pos        = (const float*)d_in[1];
    const int*   ei         = (const int*)  d_in[2];
    const float* W_in       = (const float*)d_in[3];
    const float* W_out      = (const float*)d_in[4];
    const float* pos_w1     = (const float*)d_in[5];
    const float* pos_b1     = (const float*)d_in[6];
    const float* pos_bn_g   = (const float*)d_in[7];
    const float* pos_bn_b   = (const float*)d_in[8];
    const float* pos_w2     = (const float*)d_in[9];
    const float* pos_b2     = (const float*)d_in[10];
    const float* attn_bn1_g = (const float*)d_in[11];
    const float* attn_bn1_b = (const float*)d_in[12];
    const float* attn_w1    = (const float*)d_in[13];
    const float* attn_b1    = (const float*)d_in[14];
    const float* attn_bn2_g = (const float*)d_in[15];
    const float* attn_bn2_b = (const float*)d_in[16];
    const float* attn_w2    = (const float*)d_in[17];
    const float* attn_b2    = (const float*)d_in[18];
    const float* lin_w      = (const float*)d_in[19];
    const float* lin_b      = (const float*)d_in[20];
    const float* src_w      = (const float*)d_in[21];
    const float* src_b      = (const float*)d_in[22];
    const float* dst_w      = (const float*)d_in[23];
    const float* dst_b      = (const float*)d_in[24];
    const float* bn1_g      = (const float*)d_in[25];
    const float* bn1_b      = (const float*)d_in[26];
    const float* bn2_g      = (const float*)d_in[27];
    const float* bn2_b      = (const float*)d_in[28];
    const float* bn3_g      = (const float*)d_in[29];
    const float* bn3_b      = (const float*)d_in[30];
    const int* srcp = ei;  // edge_index row 0

    float *p_y,*p_asrc,*p_adst,*p_hW,*p_out,*p_y3,*p_part,*p_wt;
    float *p_bn1s,*p_bn1t,*p_poss,*p_post,*p_ab1s,*p_ab1t,*p_ab2s,*p_ab2t,*p_bn2s,*p_bn2t,*p_bn3s,*p_bn3t;
    cudaGetSymbolAddress((void**)&p_y,    g_y);
    cudaGetSymbolAddress((void**)&p_asrc, g_asrc);
    cudaGetSymbolAddress((void**)&p_adst, g_adst);
    cudaGetSymbolAddress((void**)&p_hW,   g_hW);
    cudaGetSymbolAddress((void**)&p_out,  g_out);
    cudaGetSymbolAddress((void**)&p_y3,   g_y3);
    cudaGetSymbolAddress((void**)&p_part, g_part);
    cudaGetSymbolAddress((void**)&p_wt,   g_WT5);
    cudaGetSymbolAddress((void**)&p_bn1s, g_bn1_s); cudaGetSymbolAddress((void**)&p_bn1t, g_bn1_t);
    cudaGetSymbolAddress((void**)&p_poss, g_pos_s); cudaGetSymbolAddress((void**)&p_post, g_pos_t);
    cudaGetSymbolAddress((void**)&p_ab1s, g_ab1_s); cudaGetSymbolAddress((void**)&p_ab1t, g_ab1_t);
    cudaGetSymbolAddress((void**)&p_ab2s, g_ab2_s); cudaGetSymbolAddress((void**)&p_ab2t, g_ab2_t);
    cudaGetSymbolAddress((void**)&p_bn2s, g_bn2_s); cudaGetSymbolAddress((void**)&p_bn2t, g_bn2_t);
    cudaGetSymbolAddress((void**)&p_bn3s, g_bn3_s); cudaGetSymbolAddress((void**)&p_bn3t, g_bn3_t);

    // 0) pre-transpose weights (W_in, src_w, dst_w, lin_w, W_out)
    k_tw<<<5,256>>>(W_in, src_w, dst_w, lin_w, W_out, p_wt);
    // 1) fused: GEMM1 (bn1 partials) + pos-MLP edge pass (pos partials)
    k_front<<<2048,256>>>(x, p_wt, p_y, p_part, srcp, pos, pos_w1, pos_b1);
    k_reduce2<<<67,256>>>(p_part, bn1_g, bn1_b, p_bn1s, p_bn1t,
                          pos_bn_g, pos_bn_b, p_poss, p_post);
    // 2) fused triple GEMM on h = relu(bn1(y))
    k_gemm3<<<1024,256>>>(p_y, p_wt + 4096, p_wt + 2*4096, p_wt + 3*4096,
                          src_b, dst_b, lin_b, p_bn1s, p_bn1t, p_asrc, p_adst, p_hW);
    // 3) attn_bn1 stats (16 lanes/node, grid = NN/16)
    k_e2<<<4096,256>>>(srcp, pos_w2, pos_b2);
    k_reduce<<<64,256>>>(p_part, 4096, 64, attn_bn1_g, attn_bn1_b, (float)EE, p_ab1s, p_ab1t);
    // 4) a2pre + attn_bn2 stats (16 lanes/node, grid = NN/16)
    k_e3<<<4096,256>>>(srcp, pos_w2, pos_b2, attn_w1, attn_b1);
    k_reduce<<<64,256>>>(p_part, 4096, 8, attn_bn2_g, attn_bn2_b, (float)EE, p_ab2s, p_ab2t);
    // 5) softmax + aggregate (+ bn2 stats)
    k_e4<<<8192,256>>>(srcp, pos_w2, pos_b2, attn_w2, attn_b2);
    k_reduce<<<64,256>>>(p_part, 8192, 64, bn2_g, bn2_b, (float)NN, p_bn2s, p_bn2t);
    // 6) y3 = relu(bn2(out)) @ W_out^T (+ bn3 stats)
    k_gemm<1,1><<<1024,256>>>(p_out, p_wt + 4*4096, p_bn2s, p_bn2t, p_y3, p_part);
    k_reduce<<<64,256>>>(p_part, 1024, 64, bn3_g, bn3_b, (float)NN, p_bn3s, p_bn3t);
    // 7) final residual + relu
    k_final<<<4096,256>>>(p_y3, x, (float*)d_out);
}